// round 4
// baseline (speedup 1.0000x reference)
#include <cuda_runtime.h>
#include <cuda_bf16.h>

#define NN 50000
#define NE 800000
#define DD 64

// Scratch (static device globals)
__device__ float g_neigh[NN * DD];    // holds z = h + segment_sum(h[src])
__device__ float g_z2[NN * DD];
__device__ float g_sum[DD];
__device__ float g_sqs[DD];
__device__ int   g_cnt[NN];
__device__ int   g_rowstart[NN + 1];
__device__ int   g_cursor[NN];
__device__ int   g_esrc[NE];

// ---------------------------------------------------------------------------
// K0: zero counters + BN stat accumulators
// ---------------------------------------------------------------------------
__global__ void k_zero() {
    int i = blockIdx.x * blockDim.x + threadIdx.x;
    if (i < NN) g_cnt[i] = 0;
    if (blockIdx.x == 0 && threadIdx.x < DD) {
        g_sum[threadIdx.x] = 0.f;
        g_sqs[threadIdx.x] = 0.f;
    }
}

// ---------------------------------------------------------------------------
// K1: histogram of dst (indices are int32)
// ---------------------------------------------------------------------------
__global__ void k_hist(const int* __restrict__ dst) {
    int e = blockIdx.x * blockDim.x + threadIdx.x;
    if (e < NE) atomicAdd(&g_cnt[dst[e]], 1);
}

// ---------------------------------------------------------------------------
// K2: single-block exclusive scan: g_cnt -> g_rowstart, g_cursor
//     1024 threads, 49 counts per thread, two passes
// ---------------------------------------------------------------------------
#define SCHUNK 49
__global__ void __launch_bounds__(1024) k_scan() {
    const int t = threadIdx.x;
    const int lane = t & 31, w = t >> 5;
    const int base = t * SCHUNK;

    // pass 1: per-thread total
    int s = 0;
    #pragma unroll 7
    for (int i = 0; i < SCHUNK; i++) {
        int idx = base + i;
        if (idx < NN) s += g_cnt[idx];
    }
    // block exclusive scan of s over 1024 threads
    int v = s;
    #pragma unroll
    for (int o = 1; o < 32; o <<= 1) {
        int tmp = __shfl_up_sync(0xffffffffu, v, o);
        if (lane >= o) v += tmp;
    }
    __shared__ int ws[32], wso[32];
    if (lane == 31) ws[w] = v;
    __syncthreads();
    if (w == 0) {
        int c = ws[lane];
        int vv = c;
        #pragma unroll
        for (int o = 1; o < 32; o <<= 1) {
            int tmp = __shfl_up_sync(0xffffffffu, vv, o);
            if (lane >= o) vv += tmp;
        }
        wso[lane] = vv - c;
    }
    __syncthreads();
    int off = (v - s) + wso[w];     // exclusive prefix for this thread

    // pass 2: write rowstarts
    int r = off;
    #pragma unroll 7
    for (int i = 0; i < SCHUNK; i++) {
        int idx = base + i;
        if (idx < NN) {
            g_rowstart[idx] = r;
            g_cursor[idx] = r;
            r += g_cnt[idx];
        }
    }
    if (t == 1023) g_rowstart[NN] = NE;
}

// ---------------------------------------------------------------------------
// K3: fill CSR edge array (src ids grouped by dst)
// ---------------------------------------------------------------------------
__global__ void k_fill(const int* __restrict__ src, const int* __restrict__ dst) {
    int e = blockIdx.x * blockDim.x + threadIdx.x;
    if (e >= NE) return;
    int p = atomicAdd(&g_cursor[dst[e]], 1);
    g_esrc[p] = src[e];
}

// ---------------------------------------------------------------------------
// K4: gather-sum. One warp per node.
//     All 32 lanes batch-load up to 32 edge ids (one coalesced load),
//     broadcast via shfl; each lane owns a float2 slice of the 64-dim row.
// ---------------------------------------------------------------------------
__global__ void __launch_bounds__(256) k_gather(const float2* __restrict__ h2) {
    int wid = (blockIdx.x * blockDim.x + threadIdx.x) >> 5;
    if (wid >= NN) return;
    const int lane = threadIdx.x & 31;
    const int start = g_rowstart[wid];
    const int end = g_rowstart[wid + 1];

    // own row (eps = 0 -> z starts from h[n])
    float2 acc = __ldg(&h2[(size_t)wid * 32 + lane]);
    float2 acc2 = make_float2(0.f, 0.f);

    for (int b = start; b < end; b += 32) {
        int nb = end - b; if (nb > 32) nb = 32;
        int idx = (b + lane < end) ? g_esrc[b + lane] : 0;
        int j = 0;
        for (; j + 1 < nb; j += 2) {
            int s0 = __shfl_sync(0xffffffffu, idx, j);
            int s1 = __shfl_sync(0xffffffffu, idx, j + 1);
            float2 v0 = __ldg(&h2[(size_t)s0 * 32 + lane]);
            float2 v1 = __ldg(&h2[(size_t)s1 * 32 + lane]);
            acc.x += v0.x; acc.y += v0.y;
            acc2.x += v1.x; acc2.y += v1.y;
        }
        if (j < nb) {
            int s0 = __shfl_sync(0xffffffffu, idx, j);
            float2 v0 = __ldg(&h2[(size_t)s0 * 32 + lane]);
            acc.x += v0.x; acc.y += v0.y;
        }
    }
    acc.x += acc2.x; acc.y += acc2.y;
    ((float2*)g_neigh)[(size_t)wid * 32 + lane] = acc;
}

// ---------------------------------------------------------------------------
// K5: per-node MLP  z2 = relu(z@W1+b1)@W2+b2, fused BN-stat accumulation
//     128 nodes/block, 256 threads: each thread 8 nodes x 4 cols
// ---------------------------------------------------------------------------
__global__ void __launch_bounds__(256) k_mlp(const float* __restrict__ W1,
                                             const float* __restrict__ b1,
                                             const float* __restrict__ W2,
                                             const float* __restrict__ b2) {
    __shared__ float sZ[128 * DD];
    __shared__ float sW[DD * DD];

    const int tid = threadIdx.x;
    const int node0 = blockIdx.x * 128;
    const int nvalid = min(128, NN - node0);

    for (int i = tid; i < 128 * 16; i += 256) {
        float4 v = (i < nvalid * 16) ? ((const float4*)g_neigh)[node0 * 16 + i]
                                     : make_float4(0.f, 0.f, 0.f, 0.f);
        ((float4*)sZ)[i] = v;
    }
    for (int i = tid; i < DD * DD; i += 256) {
        int k = i >> 6, j = i & 63;
        sW[j * DD + k] = W1[i];
    }
    __syncthreads();

    const int jg = tid & 15;
    const int ng = tid >> 4;
    const int j0 = jg * 4;
    const int n0 = ng * 8;

    float acc[8][4];
    {
        float bb0 = b1[j0], bb1 = b1[j0 + 1], bb2 = b1[j0 + 2], bb3 = b1[j0 + 3];
        #pragma unroll
        for (int n = 0; n < 8; n++) {
            acc[n][0] = bb0; acc[n][1] = bb1; acc[n][2] = bb2; acc[n][3] = bb3;
        }
    }
    #pragma unroll
    for (int k0 = 0; k0 < DD; k0 += 4) {
        float4 w[4];
        #pragma unroll
        for (int c = 0; c < 4; c++)
            w[c] = *(const float4*)&sW[(j0 + c) * DD + k0];
        #pragma unroll
        for (int n = 0; n < 8; n++) {
            float4 a = *(const float4*)&sZ[(n0 + n) * DD + k0];
            #pragma unroll
            for (int c = 0; c < 4; c++) {
                acc[n][c] = fmaf(a.x, w[c].x, acc[n][c]);
                acc[n][c] = fmaf(a.y, w[c].y, acc[n][c]);
                acc[n][c] = fmaf(a.z, w[c].z, acc[n][c]);
                acc[n][c] = fmaf(a.w, w[c].w, acc[n][c]);
            }
        }
    }
    __syncthreads();

    #pragma unroll
    for (int n = 0; n < 8; n++)
        #pragma unroll
        for (int c = 0; c < 4; c++)
            sZ[(n0 + n) * DD + j0 + c] = fmaxf(acc[n][c], 0.f);
    for (int i = tid; i < DD * DD; i += 256) {
        int k = i >> 6, j = i & 63;
        sW[j * DD + k] = W2[i];
    }
    __syncthreads();

    {
        float bb0 = b2[j0], bb1 = b2[j0 + 1], bb2v = b2[j0 + 2], bb3 = b2[j0 + 3];
        #pragma unroll
        for (int n = 0; n < 8; n++) {
            acc[n][0] = bb0; acc[n][1] = bb1; acc[n][2] = bb2v; acc[n][3] = bb3;
        }
    }
    #pragma unroll
    for (int k0 = 0; k0 < DD; k0 += 4) {
        float4 w[4];
        #pragma unroll
        for (int c = 0; c < 4; c++)
            w[c] = *(const float4*)&sW[(j0 + c) * DD + k0];
        #pragma unroll
        for (int n = 0; n < 8; n++) {
            float4 a = *(const float4*)&sZ[(n0 + n) * DD + k0];
            #pragma unroll
            for (int c = 0; c < 4; c++) {
                acc[n][c] = fmaf(a.x, w[c].x, acc[n][c]);
                acc[n][c] = fmaf(a.y, w[c].y, acc[n][c]);
                acc[n][c] = fmaf(a.z, w[c].z, acc[n][c]);
                acc[n][c] = fmaf(a.w, w[c].w, acc[n][c]);
            }
        }
    }

    float s[4] = {0.f, 0.f, 0.f, 0.f};
    float q[4] = {0.f, 0.f, 0.f, 0.f};
    #pragma unroll
    for (int n = 0; n < 8; n++) {
        int node = node0 + n0 + n;
        if (node < NN) {
            ((float4*)g_z2)[node * 16 + jg] =
                make_float4(acc[n][0], acc[n][1], acc[n][2], acc[n][3]);
            #pragma unroll
            for (int c = 0; c < 4; c++) {
                float v = acc[n][c];
                s[c] += v;
                q[c] += v * v;
            }
        }
    }

    __syncthreads();
    float* sRed = sW;
    #pragma unroll
    for (int c = 0; c < 4; c++) {
        sRed[tid * 8 + c] = s[c];
        sRed[tid * 8 + 4 + c] = q[c];
    }
    __syncthreads();
    if (tid < DD) {
        int jg2 = tid >> 2, c2 = tid & 3;
        float a = 0.f, b = 0.f;
        #pragma unroll
        for (int g = 0; g < 16; g++) {
            int t2 = jg2 + g * 16;
            a += sRed[t2 * 8 + c2];
            b += sRed[t2 * 8 + 4 + c2];
        }
        atomicAdd(&g_sum[tid], a);
        atomicAdd(&g_sqs[tid], b);
    }
}

// ---------------------------------------------------------------------------
// K6: out = h + relu( z2 * scale + shift )
// ---------------------------------------------------------------------------
__global__ void k_bn(const float4* __restrict__ h4,
                     const float* __restrict__ gamma,
                     const float* __restrict__ beta,
                     float4* __restrict__ out4) {
    __shared__ float sA[DD], sB[DD];
    if (threadIdx.x < DD) {
        const float invN = 1.0f / (float)NN;
        float m = g_sum[threadIdx.x] * invN;
        float v = g_sqs[threadIdx.x] * invN - m * m;
        float a = gamma[threadIdx.x] * rsqrtf(v + 1e-5f);
        sA[threadIdx.x] = a;
        sB[threadIdx.x] = beta[threadIdx.x] - m * a;
    }
    __syncthreads();
    int i = blockIdx.x * blockDim.x + threadIdx.x;
    if (i < NN * 16) {
        float4 z = ((const float4*)g_z2)[i];
        float4 hv = h4[i];
        int dg = (i & 15) * 4;
        float4 o;
        o.x = hv.x + fmaxf(fmaf(z.x, sA[dg + 0], sB[dg + 0]), 0.f);
        o.y = hv.y + fmaxf(fmaf(z.y, sA[dg + 1], sB[dg + 1]), 0.f);
        o.z = hv.z + fmaxf(fmaf(z.z, sA[dg + 2], sB[dg + 2]), 0.f);
        o.w = hv.w + fmaxf(fmaf(z.w, sA[dg + 3], sB[dg + 3]), 0.f);
        out4[i] = o;
    }
}

// ---------------------------------------------------------------------------
extern "C" void kernel_launch(void* const* d_in, const int* in_sizes, int n_in,
                              void* d_out, int out_size) {
    const float* h     = (const float*)d_in[0];
    const float* W1    = (const float*)d_in[1];
    const float* b1    = (const float*)d_in[2];
    const float* W2    = (const float*)d_in[3];
    const float* b2    = (const float*)d_in[4];
    const float* gamma = (const float*)d_in[5];
    const float* beta  = (const float*)d_in[6];
    const int* src     = (const int*)d_in[7];
    const int* dst     = (const int*)d_in[8];

    (void)in_sizes; (void)n_in; (void)out_size;

    const int eblocks = (NE + 255) / 256;       // 3125

    k_zero<<<(NN + 255) / 256, 256>>>();
    k_hist<<<eblocks, 256>>>(dst);
    k_scan<<<1, 1024>>>();
    k_fill<<<eblocks, 256>>>(src, dst);
    k_gather<<<(NN * 32 + 255) / 256, 256>>>((const float2*)h);
    k_mlp<<<(NN + 127) / 128, 256>>>(W1, b1, W2, b2);
    k_bn<<<(NN * 16 + 255) / 256, 256>>>((const float4*)h, gamma, beta, (float4*)d_out);
}

// round 5
// speedup vs baseline: 1.5064x; 1.5064x over previous
#include <cuda_runtime.h>
#include <cuda_bf16.h>

#define NN 50000
#define NE 800000
#define DD 64
#define CAP 64            // max in-degree slots (P(deg>=64) ~ 3e-22 for Poisson(16))

// Scratch (static device globals)
__device__ float g_neigh[NN * DD];    // z = h + segment_sum(h[src])
__device__ float g_z2[NN * DD];
__device__ float g_sum[DD];
__device__ float g_sqs[DD];
__device__ int   g_cnt[NN];
__device__ int   g_slot[NN * CAP];

// ---------------------------------------------------------------------------
// K0: zero per-node counters + BN stat accumulators
// ---------------------------------------------------------------------------
__global__ void k_zero() {
    int i = blockIdx.x * blockDim.x + threadIdx.x;
    if (i < NN) g_cnt[i] = 0;
    if (blockIdx.x == 0 && threadIdx.x < DD) {
        g_sum[threadIdx.x] = 0.f;
        g_sqs[threadIdx.x] = 0.f;
    }
}

// ---------------------------------------------------------------------------
// K1: bucket fill — slot[dst][p] = src  (indices are int32)
// ---------------------------------------------------------------------------
__global__ void k_fill(const int* __restrict__ src, const int* __restrict__ dst) {
    int e = blockIdx.x * blockDim.x + threadIdx.x;
    if (e >= NE) return;
    int d = dst[e];
    int p = atomicAdd(&g_cnt[d], 1);
    if (p < CAP) g_slot[d * CAP + p] = src[e];
}

// ---------------------------------------------------------------------------
// K2: gather-sum with ILP=8. One warp per node; lane owns a float2 slice.
//     All edge ids preloaded (2 regs/lane), shfl-broadcast; 8 independent
//     256B row loads in flight per iteration.
// ---------------------------------------------------------------------------
__global__ void __launch_bounds__(128) k_gather(const float2* __restrict__ h2) {
    int node = (blockIdx.x * blockDim.x + threadIdx.x) >> 5;
    if (node >= NN) return;
    const int lane = threadIdx.x & 31;

    int deg = g_cnt[node];
    if (deg > CAP) deg = CAP;
    const int* sl = &g_slot[node * CAP];
    int idx0 = sl[lane];          // edges 0..31 (may be junk past deg; guarded)
    int idx1 = sl[32 + lane];     // edges 32..63

    float2 acc0 = __ldg(&h2[(size_t)node * 32 + lane]);   // eps=0 -> start at h[n]
    float2 acc1 = make_float2(0.f, 0.f);
    float2 acc2 = make_float2(0.f, 0.f);
    float2 acc3 = make_float2(0.f, 0.f);

    for (int j = 0; j < deg; j += 8) {
        int m = deg - j;                       // >= 1, uniform across warp
        float2 v[8];
        #pragma unroll
        for (int k = 0; k < 8; k++) {
            int e = j + k;
            int reg = (e < 32) ? idx0 : idx1;  // e uniform -> uniform select
            int s = __shfl_sync(0xffffffffu, reg, e & 31);
            v[k] = make_float2(0.f, 0.f);
            if (k < m) v[k] = __ldg(&h2[(size_t)s * 32 + lane]);
        }
        acc0.x += v[0].x; acc0.y += v[0].y;
        acc1.x += v[1].x; acc1.y += v[1].y;
        acc2.x += v[2].x; acc2.y += v[2].y;
        acc3.x += v[3].x; acc3.y += v[3].y;
        acc0.x += v[4].x; acc0.y += v[4].y;
        acc1.x += v[5].x; acc1.y += v[5].y;
        acc2.x += v[6].x; acc2.y += v[6].y;
        acc3.x += v[7].x; acc3.y += v[7].y;
    }
    acc0.x += acc1.x + acc2.x + acc3.x;
    acc0.y += acc1.y + acc2.y + acc3.y;
    ((float2*)g_neigh)[(size_t)node * 32 + lane] = acc0;
}

// ---------------------------------------------------------------------------
// K3: per-node MLP  z2 = relu(z@W1+b1)@W2+b2, fused BN-stat accumulation
//     128 nodes/block, 256 threads: each thread 8 nodes x 4 cols
// ---------------------------------------------------------------------------
__global__ void __launch_bounds__(256) k_mlp(const float* __restrict__ W1,
                                             const float* __restrict__ b1,
                                             const float* __restrict__ W2,
                                             const float* __restrict__ b2) {
    __shared__ float sZ[128 * DD];
    __shared__ float sW[DD * DD];

    const int tid = threadIdx.x;
    const int node0 = blockIdx.x * 128;
    const int nvalid = min(128, NN - node0);

    for (int i = tid; i < 128 * 16; i += 256) {
        float4 v = (i < nvalid * 16) ? ((const float4*)g_neigh)[node0 * 16 + i]
                                     : make_float4(0.f, 0.f, 0.f, 0.f);
        ((float4*)sZ)[i] = v;
    }
    for (int i = tid; i < DD * DD; i += 256) {
        int k = i >> 6, j = i & 63;
        sW[j * DD + k] = W1[i];
    }
    __syncthreads();

    const int jg = tid & 15;
    const int ng = tid >> 4;
    const int j0 = jg * 4;
    const int n0 = ng * 8;

    float acc[8][4];
    {
        float bb0 = b1[j0], bb1 = b1[j0 + 1], bb2 = b1[j0 + 2], bb3 = b1[j0 + 3];
        #pragma unroll
        for (int n = 0; n < 8; n++) {
            acc[n][0] = bb0; acc[n][1] = bb1; acc[n][2] = bb2; acc[n][3] = bb3;
        }
    }
    #pragma unroll
    for (int k0 = 0; k0 < DD; k0 += 4) {
        float4 w[4];
        #pragma unroll
        for (int c = 0; c < 4; c++)
            w[c] = *(const float4*)&sW[(j0 + c) * DD + k0];
        #pragma unroll
        for (int n = 0; n < 8; n++) {
            float4 a = *(const float4*)&sZ[(n0 + n) * DD + k0];
            #pragma unroll
            for (int c = 0; c < 4; c++) {
                acc[n][c] = fmaf(a.x, w[c].x, acc[n][c]);
                acc[n][c] = fmaf(a.y, w[c].y, acc[n][c]);
                acc[n][c] = fmaf(a.z, w[c].z, acc[n][c]);
                acc[n][c] = fmaf(a.w, w[c].w, acc[n][c]);
            }
        }
    }
    __syncthreads();

    #pragma unroll
    for (int n = 0; n < 8; n++)
        #pragma unroll
        for (int c = 0; c < 4; c++)
            sZ[(n0 + n) * DD + j0 + c] = fmaxf(acc[n][c], 0.f);
    for (int i = tid; i < DD * DD; i += 256) {
        int k = i >> 6, j = i & 63;
        sW[j * DD + k] = W2[i];
    }
    __syncthreads();

    {
        float bb0 = b2[j0], bb1 = b2[j0 + 1], bb2v = b2[j0 + 2], bb3 = b2[j0 + 3];
        #pragma unroll
        for (int n = 0; n < 8; n++) {
            acc[n][0] = bb0; acc[n][1] = bb1; acc[n][2] = bb2v; acc[n][3] = bb3;
        }
    }
    #pragma unroll
    for (int k0 = 0; k0 < DD; k0 += 4) {
        float4 w[4];
        #pragma unroll
        for (int c = 0; c < 4; c++)
            w[c] = *(const float4*)&sW[(j0 + c) * DD + k0];
        #pragma unroll
        for (int n = 0; n < 8; n++) {
            float4 a = *(const float4*)&sZ[(n0 + n) * DD + k0];
            #pragma unroll
            for (int c = 0; c < 4; c++) {
                acc[n][c] = fmaf(a.x, w[c].x, acc[n][c]);
                acc[n][c] = fmaf(a.y, w[c].y, acc[n][c]);
                acc[n][c] = fmaf(a.z, w[c].z, acc[n][c]);
                acc[n][c] = fmaf(a.w, w[c].w, acc[n][c]);
            }
        }
    }

    float s[4] = {0.f, 0.f, 0.f, 0.f};
    float q[4] = {0.f, 0.f, 0.f, 0.f};
    #pragma unroll
    for (int n = 0; n < 8; n++) {
        int node = node0 + n0 + n;
        if (node < NN) {
            ((float4*)g_z2)[node * 16 + jg] =
                make_float4(acc[n][0], acc[n][1], acc[n][2], acc[n][3]);
            #pragma unroll
            for (int c = 0; c < 4; c++) {
                float v = acc[n][c];
                s[c] += v;
                q[c] += v * v;
            }
        }
    }

    __syncthreads();
    float* sRed = sW;
    #pragma unroll
    for (int c = 0; c < 4; c++) {
        sRed[tid * 8 + c] = s[c];
        sRed[tid * 8 + 4 + c] = q[c];
    }
    __syncthreads();
    if (tid < DD) {
        int jg2 = tid >> 2, c2 = tid & 3;
        float a = 0.f, b = 0.f;
        #pragma unroll
        for (int g = 0; g < 16; g++) {
            int t2 = jg2 + g * 16;
            a += sRed[t2 * 8 + c2];
            b += sRed[t2 * 8 + 4 + c2];
        }
        atomicAdd(&g_sum[tid], a);
        atomicAdd(&g_sqs[tid], b);
    }
}

// ---------------------------------------------------------------------------
// K4: out = h + relu( z2 * scale + shift )
// ---------------------------------------------------------------------------
__global__ void k_bn(const float4* __restrict__ h4,
                     const float* __restrict__ gamma,
                     const float* __restrict__ beta,
                     float4* __restrict__ out4) {
    __shared__ float sA[DD], sB[DD];
    if (threadIdx.x < DD) {
        const float invN = 1.0f / (float)NN;
        float m = g_sum[threadIdx.x] * invN;
        float v = g_sqs[threadIdx.x] * invN - m * m;
        float a = gamma[threadIdx.x] * rsqrtf(v + 1e-5f);
        sA[threadIdx.x] = a;
        sB[threadIdx.x] = beta[threadIdx.x] - m * a;
    }
    __syncthreads();
    int i = blockIdx.x * blockDim.x + threadIdx.x;
    if (i < NN * 16) {
        float4 z = ((const float4*)g_z2)[i];
        float4 hv = h4[i];
        int dg = (i & 15) * 4;
        float4 o;
        o.x = hv.x + fmaxf(fmaf(z.x, sA[dg + 0], sB[dg + 0]), 0.f);
        o.y = hv.y + fmaxf(fmaf(z.y, sA[dg + 1], sB[dg + 1]), 0.f);
        o.z = hv.z + fmaxf(fmaf(z.z, sA[dg + 2], sB[dg + 2]), 0.f);
        o.w = hv.w + fmaxf(fmaf(z.w, sA[dg + 3], sB[dg + 3]), 0.f);
        out4[i] = o;
    }
}

// ---------------------------------------------------------------------------
extern "C" void kernel_launch(void* const* d_in, const int* in_sizes, int n_in,
                              void* d_out, int out_size) {
    const float* h     = (const float*)d_in[0];
    const float* W1    = (const float*)d_in[1];
    const float* b1    = (const float*)d_in[2];
    const float* W2    = (const float*)d_in[3];
    const float* b2    = (const float*)d_in[4];
    const float* gamma = (const float*)d_in[5];
    const float* beta  = (const float*)d_in[6];
    const int* src     = (const int*)d_in[7];
    const int* dst     = (const int*)d_in[8];

    (void)in_sizes; (void)n_in; (void)out_size;

    k_zero<<<(NN + 255) / 256, 256>>>();
    k_fill<<<(NE + 255) / 256, 256>>>(src, dst);
    k_gather<<<(NN * 32 + 127) / 128, 128>>>((const float2*)h);
    k_mlp<<<(NN + 127) / 128, 256>>>(W1, b1, W2, b2);
    k_bn<<<(NN * 16 + 255) / 256, 256>>>((const float4*)h, gamma, beta, (float4*)d_out);
}

// round 8
// speedup vs baseline: 2.1046x; 1.3971x over previous
#include <cuda_runtime.h>
#include <cuda_bf16.h>

#define NN 50000
#define NE 800000
#define DD 64

// Scratch (static device globals)
__device__ float g_neigh[NN * DD];    // z = h + segment_sum(h[src])
__device__ float g_z2[NN * DD];
__device__ float g_sum[DD];
__device__ float g_sqs[DD];

// ---------------------------------------------------------------------------
// K1: neigh = h (eps=0), zero BN stat accumulators
// ---------------------------------------------------------------------------
__global__ void k_init(const float4* __restrict__ h4) {
    int i = blockIdx.x * blockDim.x + threadIdx.x;
    if (i < NN * 16) ((float4*)g_neigh)[i] = h4[i];
    if (blockIdx.x == 0 && threadIdx.x < DD) {
        g_sum[threadIdx.x] = 0.f;
        g_sqs[threadIdx.x] = 0.f;
    }
}

// ---------------------------------------------------------------------------
// K2: scatter-add  neigh[dst] += h[src]  (16 lanes/edge, RED.v4, int32 idx)
// ---------------------------------------------------------------------------
__global__ void k_scatter(const float4* __restrict__ h4,
                          const int* __restrict__ src,
                          const int* __restrict__ dst) {
    int t = blockIdx.x * blockDim.x + threadIdx.x;
    int e = t >> 4;
    int part = t & 15;
    if (e >= NE) return;
    int s = src[e];
    int d = dst[e];
    float4 v = __ldg(&h4[(size_t)s * 16 + part]);
    float* p = &g_neigh[(size_t)d * DD + part * 4];
    asm volatile("red.global.add.v4.f32 [%0], {%1,%2,%3,%4};"
                 :: "l"(p), "f"(v.x), "f"(v.y), "f"(v.z), "f"(v.w)
                 : "memory");
}

// ---------------------------------------------------------------------------
// XOR-swizzled sZ addressing: float4 column c4 of row r lives at c4^(r&15).
// Node-indexed accesses (rows = lane) hit distinct banks per 8-lane phase.
// ---------------------------------------------------------------------------
__device__ __forceinline__ int zoff(int row, int c4) {
    return row * DD + ((c4 ^ (row & 15)) << 2);
}

// ---------------------------------------------------------------------------
// K3: MLP  z2 = relu(z@W1+b1)@W2+b2, fused BN-stat accumulation.
//     128 nodes/block, 256 thr (8 warps). warp w -> cols w*8..w*8+7 (weight
//     loads warp-uniform => broadcast); lane -> nodes lane+{0,32,64,96}.
//     smem: sZ 32KB (swizzled) + sW 16KB = 48KB.
// ---------------------------------------------------------------------------
__global__ void __launch_bounds__(256, 2) k_mlp(const float* __restrict__ W1,
                                                const float* __restrict__ b1,
                                                const float* __restrict__ W2,
                                                const float* __restrict__ b2) {
    __shared__ float sZ[128 * DD];    // 32 KB, xor-swizzled rows
    __shared__ float sW[DD * DD];     // 16 KB, sW[c*64+k] = W[k][c]

    const int tid = threadIdx.x;
    const int node0 = blockIdx.x * 128;
    const int nvalid = min(128, NN - node0);

    // load z tile (swizzled store); zero-fill tail rows
    for (int i = tid; i < 128 * 16; i += 256) {
        int nd = i >> 4, p = i & 15;
        float4 v = (i < nvalid * 16) ? ((const float4*)g_neigh)[node0 * 16 + i]
                                     : make_float4(0.f, 0.f, 0.f, 0.f);
        *(float4*)&sZ[zoff(nd, p)] = v;
    }
    // sW[c][k] = W1[k][c]
    for (int i = tid; i < DD * DD; i += 256) {
        int k = i >> 6, c = i & 63;
        sW[c * DD + k] = W1[i];
    }
    __syncthreads();

    const int warp = tid >> 5, lane = tid & 31;
    const int c0 = warp * 8;

    float acc[4][8];
    #pragma unroll
    for (int c = 0; c < 8; c++) {
        float bb = b1[c0 + c];
        #pragma unroll
        for (int g = 0; g < 4; g++) acc[g][c] = bb;
    }

    // ---- layer 1 ----
    #pragma unroll
    for (int k = 0; k < DD; k += 4) {
        float4 w[8];
        #pragma unroll
        for (int c = 0; c < 8; c++) w[c] = *(const float4*)&sW[(c0 + c) * DD + k];
        float4 a[4];
        #pragma unroll
        for (int g = 0; g < 4; g++) a[g] = *(const float4*)&sZ[zoff(lane + 32 * g, k >> 2)];
        #pragma unroll
        for (int g = 0; g < 4; g++)
            #pragma unroll
            for (int c = 0; c < 8; c++) {
                acc[g][c] = fmaf(a[g].x, w[c].x, acc[g][c]);
                acc[g][c] = fmaf(a[g].y, w[c].y, acc[g][c]);
                acc[g][c] = fmaf(a[g].z, w[c].z, acc[g][c]);
                acc[g][c] = fmaf(a[g].w, w[c].w, acc[g][c]);
            }
    }
    __syncthreads();   // everyone done reading sZ/sW for layer 1

    // write relu(y1) back to sZ (cols c0..c0+7 of own nodes); reload sW = W2^T
    #pragma unroll
    for (int g = 0; g < 4; g++) {
        int row = lane + 32 * g;
        *(float4*)&sZ[zoff(row, c0 >> 2)] =
            make_float4(fmaxf(acc[g][0], 0.f), fmaxf(acc[g][1], 0.f),
                        fmaxf(acc[g][2], 0.f), fmaxf(acc[g][3], 0.f));
        *(float4*)&sZ[zoff(row, (c0 >> 2) + 1)] =
            make_float4(fmaxf(acc[g][4], 0.f), fmaxf(acc[g][5], 0.f),
                        fmaxf(acc[g][6], 0.f), fmaxf(acc[g][7], 0.f));
    }
    for (int i = tid; i < DD * DD; i += 256) {
        int k = i >> 6, c = i & 63;
        sW[c * DD + k] = W2[i];
    }
    __syncthreads();

    // ---- layer 2 ----
    #pragma unroll
    for (int c = 0; c < 8; c++) {
        float bb = b2[c0 + c];
        #pragma unroll
        for (int g = 0; g < 4; g++) acc[g][c] = bb;
    }
    #pragma unroll
    for (int k = 0; k < DD; k += 4) {
        float4 w[8];
        #pragma unroll
        for (int c = 0; c < 8; c++) w[c] = *(const float4*)&sW[(c0 + c) * DD + k];
        float4 a[4];
        #pragma unroll
        for (int g = 0; g < 4; g++) a[g] = *(const float4*)&sZ[zoff(lane + 32 * g, k >> 2)];
        #pragma unroll
        for (int g = 0; g < 4; g++)
            #pragma unroll
            for (int c = 0; c < 8; c++) {
                acc[g][c] = fmaf(a[g].x, w[c].x, acc[g][c]);
                acc[g][c] = fmaf(a[g].y, w[c].y, acc[g][c]);
                acc[g][c] = fmaf(a[g].z, w[c].z, acc[g][c]);
                acc[g][c] = fmaf(a[g].w, w[c].w, acc[g][c]);
            }
    }

    // store z2 + per-thread BN partials over its (<=4) valid nodes
    float s[8], q[8];
    #pragma unroll
    for (int c = 0; c < 8; c++) { s[c] = 0.f; q[c] = 0.f; }
    #pragma unroll
    for (int g = 0; g < 4; g++) {
        int node = node0 + lane + 32 * g;
        if (node < NN) {
            ((float4*)g_z2)[(size_t)node * 16 + (c0 >> 2)] =
                make_float4(acc[g][0], acc[g][1], acc[g][2], acc[g][3]);
            ((float4*)g_z2)[(size_t)node * 16 + (c0 >> 2) + 1] =
                make_float4(acc[g][4], acc[g][5], acc[g][6], acc[g][7]);
            #pragma unroll
            for (int c = 0; c < 8; c++) {
                float v = acc[g][c];
                s[c] += v;
                q[c] += v * v;
            }
        }
    }
    // warp butterfly reduce over lanes (each col independently)
    #pragma unroll
    for (int o = 16; o > 0; o >>= 1) {
        #pragma unroll
        for (int c = 0; c < 8; c++) {
            s[c] += __shfl_xor_sync(0xffffffffu, s[c], o);
            q[c] += __shfl_xor_sync(0xffffffffu, q[c], o);
        }
    }
    if (lane == 0) {
        #pragma unroll
        for (int c = 0; c < 8; c++) {
            atomicAdd(&g_sum[c0 + c], s[c]);
            atomicAdd(&g_sqs[c0 + c], q[c]);
        }
    }
}

// ---------------------------------------------------------------------------
// K4: out = h + relu( z2 * scale + shift )
// ---------------------------------------------------------------------------
__global__ void k_bn(const float4* __restrict__ h4,
                     const float* __restrict__ gamma,
                     const float* __restrict__ beta,
                     float4* __restrict__ out4) {
    __shared__ float sA[DD], sB[DD];
    if (threadIdx.x < DD) {
        const float invN = 1.0f / (float)NN;
        float m = g_sum[threadIdx.x] * invN;
        float v = g_sqs[threadIdx.x] * invN - m * m;
        float a = gamma[threadIdx.x] * rsqrtf(v + 1e-5f);
        sA[threadIdx.x] = a;
        sB[threadIdx.x] = beta[threadIdx.x] - m * a;
    }
    __syncthreads();
    int i = blockIdx.x * blockDim.x + threadIdx.x;
    if (i < NN * 16) {
        float4 z = ((const float4*)g_z2)[i];
        float4 hv = h4[i];
        int dg = (i & 15) * 4;
        float4 o;
        o.x = hv.x + fmaxf(fmaf(z.x, sA[dg + 0], sB[dg + 0]), 0.f);
        o.y = hv.y + fmaxf(fmaf(z.y, sA[dg + 1], sB[dg + 1]), 0.f);
        o.z = hv.z + fmaxf(fmaf(z.z, sA[dg + 2], sB[dg + 2]), 0.f);
        o.w = hv.w + fmaxf(fmaf(z.w, sA[dg + 3], sB[dg + 3]), 0.f);
        out4[i] = o;
    }
}

// ---------------------------------------------------------------------------
extern "C" void kernel_launch(void* const* d_in, const int* in_sizes, int n_in,
                              void* d_out, int out_size) {
    const float* h     = (const float*)d_in[0];
    const float* W1    = (const float*)d_in[1];
    const float* b1    = (const float*)d_in[2];
    const float* W2    = (const float*)d_in[3];
    const float* b2    = (const float*)d_in[4];
    const float* gamma = (const float*)d_in[5];
    const float* beta  = (const float*)d_in[6];
    const int* src     = (const int*)d_in[7];
    const int* dst     = (const int*)d_in[8];

    (void)in_sizes; (void)n_in; (void)out_size;

    k_init<<<(NN * 16 + 255) / 256, 256>>>((const float4*)h);
    k_scatter<<<(NE * 16 + 255) / 256, 256>>>((const float4*)h, src, dst);
    k_mlp<<<(NN + 127) / 128, 256>>>(W1, b1, W2, b2);
    k_bn<<<(NN * 16 + 255) / 256, 256>>>((const float4*)h, gamma, beta, (float4*)d_out);
}

// round 9
// speedup vs baseline: 2.8710x; 1.3642x over previous
#include <cuda_runtime.h>
#include <cuda_bf16.h>

#define NN 50000
#define NE 800000
#define DD 64

// Scratch (static device globals)
__device__ float g_neigh[NN * DD];    // z = h + segment_sum(h[src])
__device__ float g_z2[NN * DD];
__device__ float g_sum[DD];
__device__ float g_sqs[DD];

// ---------------------------------------------------------------------------
// K1: neigh = h (eps=0), zero BN stat accumulators
// ---------------------------------------------------------------------------
__global__ void k_init(const float4* __restrict__ h4) {
    int i = blockIdx.x * blockDim.x + threadIdx.x;
    if (i < NN * 16) ((float4*)g_neigh)[i] = h4[i];
    if (blockIdx.x == 0 && threadIdx.x < DD) {
        g_sum[threadIdx.x] = 0.f;
        g_sqs[threadIdx.x] = 0.f;
    }
}

// ---------------------------------------------------------------------------
// K2: scatter-add  neigh[dst] += h[src]  (16 lanes/edge, RED.v4, int32 idx)
// ---------------------------------------------------------------------------
__global__ void k_scatter(const float4* __restrict__ h4,
                          const int* __restrict__ src,
                          const int* __restrict__ dst) {
    int t = blockIdx.x * blockDim.x + threadIdx.x;
    int e = t >> 4;
    int part = t & 15;
    if (e >= NE) return;
    int s = src[e];
    int d = dst[e];
    float4 v = __ldg(&h4[(size_t)s * 16 + part]);
    float* p = &g_neigh[(size_t)d * DD + part * 4];
    asm volatile("red.global.add.v4.f32 [%0], {%1,%2,%3,%4};"
                 :: "l"(p), "f"(v.x), "f"(v.y), "f"(v.z), "f"(v.w)
                 : "memory");
}

// ---------------------------------------------------------------------------
// tf32 helpers + swizzled smem addressing
// ---------------------------------------------------------------------------
__device__ __forceinline__ unsigned f2tf(float x) {
    unsigned r;
    asm("cvt.rna.tf32.f32 %0, %1;" : "=r"(r) : "f"(x));
    return r;
}
// sZ: word (r,c) at r*64 + (((c>>2) ^ (r&7))<<2 | (c&3))
__device__ __forceinline__ int zidx(int r, int c) {
    return r * DD + (((((c >> 2) ^ (r & 7))) << 2) | (c & 3));
}
// sW: word (k,n) at k*64 + (n ^ ((k&3)<<3))
__device__ __forceinline__ int widx(int k, int n) {
    return k * DD + (n ^ ((k & 3) << 3));
}

__device__ __forceinline__ void mma_tf32(float c[4], unsigned a0, unsigned a1,
                                         unsigned a2, unsigned a3,
                                         unsigned b0, unsigned b1) {
    asm volatile(
        "mma.sync.aligned.m16n8k8.row.col.f32.tf32.tf32.f32 "
        "{%0,%1,%2,%3}, {%4,%5,%6,%7}, {%8,%9}, {%0,%1,%2,%3};"
        : "+f"(c[0]), "+f"(c[1]), "+f"(c[2]), "+f"(c[3])
        : "r"(a0), "r"(a1), "r"(a2), "r"(a3), "r"(b0), "r"(b1));
}

// ---------------------------------------------------------------------------
// K3: MLP via tf32 tensor cores. 128 nodes/block, 8 warps; warp w owns rows
//     16w..16w+15, computes all 64 cols as 8 m16n8k8 tiles per k-step.
// ---------------------------------------------------------------------------
__global__ void __launch_bounds__(256) k_mlp(const float* __restrict__ W1,
                                             const float* __restrict__ b1,
                                             const float* __restrict__ W2,
                                             const float* __restrict__ b2) {
    __shared__ float sZ[128 * DD];   // 32 KB, swizzled, tf32 values
    __shared__ float sW[DD * DD];    // 16 KB, swizzled, tf32 values

    const int tid = threadIdx.x;
    const int node0 = blockIdx.x * 128;
    const int nvalid = min(128, NN - node0);

    // load Z tile (cvt to tf32, swizzled store); zero-fill tail rows
    for (int i = tid; i < 128 * 16; i += 256) {
        int nd = i >> 4, p = i & 15;
        float4 v = (i < nvalid * 16) ? ((const float4*)g_neigh)[node0 * 16 + i]
                                     : make_float4(0.f, 0.f, 0.f, 0.f);
        v.x = __uint_as_float(f2tf(v.x));
        v.y = __uint_as_float(f2tf(v.y));
        v.z = __uint_as_float(f2tf(v.z));
        v.w = __uint_as_float(f2tf(v.w));
        *(float4*)&sZ[nd * DD + ((p ^ (nd & 7)) << 2)] = v;
    }
    for (int i = tid; i < DD * DD; i += 256) {
        int k = i >> 6, n = i & 63;
        sW[widx(k, n)] = __uint_as_float(f2tf(W1[i]));
    }
    __syncthreads();

    const int warp = tid >> 5, lane = tid & 31;
    const int qid = lane >> 2;    // 0..7  (row within tile / n within tile)
    const int qtid = lane & 3;    // 0..3  (col within k / k within tile)
    const int r0 = warp * 16 + qid;

    float acc[8][4];
    #pragma unroll
    for (int nt = 0; nt < 8; nt++) {
        int cc = nt * 8 + 2 * qtid;
        float bb0 = __ldg(&b1[cc]), bb1 = __ldg(&b1[cc + 1]);
        acc[nt][0] = bb0; acc[nt][1] = bb1; acc[nt][2] = bb0; acc[nt][3] = bb1;
    }

    // ---- layer 1 ----
    #pragma unroll
    for (int ks = 0; ks < 8; ks++) {
        int kc = ks * 8 + qtid;
        unsigned a0 = __float_as_uint(sZ[zidx(r0,     kc)]);
        unsigned a1 = __float_as_uint(sZ[zidx(r0 + 8, kc)]);
        unsigned a2 = __float_as_uint(sZ[zidx(r0,     kc + 4)]);
        unsigned a3 = __float_as_uint(sZ[zidx(r0 + 8, kc + 4)]);
        #pragma unroll
        for (int nt = 0; nt < 8; nt++) {
            unsigned bb0 = __float_as_uint(sW[widx(kc,     nt * 8 + qid)]);
            unsigned bb1 = __float_as_uint(sW[widx(kc + 4, nt * 8 + qid)]);
            mma_tf32(acc[nt], a0, a1, a2, a3, bb0, bb1);
        }
    }
    __syncthreads();   // everyone done reading sW (W1); sZ rows are warp-private

    // relu + cvt, write back to own sZ rows; reload sW = W2
    #pragma unroll
    for (int nt = 0; nt < 8; nt++) {
        int cc = nt * 8 + 2 * qtid;
        float2 v0, v1;
        v0.x = __uint_as_float(f2tf(fmaxf(acc[nt][0], 0.f)));
        v0.y = __uint_as_float(f2tf(fmaxf(acc[nt][1], 0.f)));
        v1.x = __uint_as_float(f2tf(fmaxf(acc[nt][2], 0.f)));
        v1.y = __uint_as_float(f2tf(fmaxf(acc[nt][3], 0.f)));
        *(float2*)&sZ[zidx(r0,     cc)] = v0;
        *(float2*)&sZ[zidx(r0 + 8, cc)] = v1;
    }
    for (int i = tid; i < DD * DD; i += 256) {
        int k = i >> 6, n = i & 63;
        sW[widx(k, n)] = __uint_as_float(f2tf(W2[i]));
    }
    __syncthreads();

    // ---- layer 2 ----
    #pragma unroll
    for (int nt = 0; nt < 8; nt++) {
        int cc = nt * 8 + 2 * qtid;
        float bb0 = __ldg(&b2[cc]), bb1 = __ldg(&b2[cc + 1]);
        acc[nt][0] = bb0; acc[nt][1] = bb1; acc[nt][2] = bb0; acc[nt][3] = bb1;
    }
    #pragma unroll
    for (int ks = 0; ks < 8; ks++) {
        int kc = ks * 8 + qtid;
        unsigned a0 = __float_as_uint(sZ[zidx(r0,     kc)]);
        unsigned a1 = __float_as_uint(sZ[zidx(r0 + 8, kc)]);
        unsigned a2 = __float_as_uint(sZ[zidx(r0,     kc + 4)]);
        unsigned a3 = __float_as_uint(sZ[zidx(r0 + 8, kc + 4)]);
        #pragma unroll
        for (int nt = 0; nt < 8; nt++) {
            unsigned bb0 = __float_as_uint(sW[widx(kc,     nt * 8 + qid)]);
            unsigned bb1 = __float_as_uint(sW[widx(kc + 4, nt * 8 + qid)]);
            mma_tf32(acc[nt], a0, a1, a2, a3, bb0, bb1);
        }
    }
    __syncthreads();   // done reading sW -> reuse as reduction scratch

    // store z2 + per-thread BN partials (guard tail rows)
    const int gr0 = node0 + warp * 16 + qid;
    const int gr1 = gr0 + 8;
    float sS[8][2], sQ[8][2];
    #pragma unroll
    for (int nt = 0; nt < 8; nt++) {
        int cc = nt * 8 + 2 * qtid;
        float c0 = acc[nt][0], c1 = acc[nt][1], c2 = acc[nt][2], c3 = acc[nt][3];
        float s0 = 0.f, s1 = 0.f, q0 = 0.f, q1 = 0.f;
        if (gr0 < NN) {
            *(float2*)&g_z2[(size_t)gr0 * DD + cc] = make_float2(c0, c1);
            s0 += c0; s1 += c1; q0 += c0 * c0; q1 += c1 * c1;
        }
        if (gr1 < NN) {
            *(float2*)&g_z2[(size_t)gr1 * DD + cc] = make_float2(c2, c3);
            s0 += c2; s1 += c3; q0 += c2 * c2; q1 += c3 * c3;
        }
        sS[nt][0] = s0; sS[nt][1] = s1; sQ[nt][0] = q0; sQ[nt][1] = q1;
    }
    // reduce over row-groups (lanes differing in bits 2..4 share columns)
    #pragma unroll
    for (int o = 4; o < 32; o <<= 1) {
        #pragma unroll
        for (int nt = 0; nt < 8; nt++) {
            sS[nt][0] += __shfl_xor_sync(0xffffffffu, sS[nt][0], o);
            sS[nt][1] += __shfl_xor_sync(0xffffffffu, sS[nt][1], o);
            sQ[nt][0] += __shfl_xor_sync(0xffffffffu, sQ[nt][0], o);
            sQ[nt][1] += __shfl_xor_sync(0xffffffffu, sQ[nt][1], o);
        }
    }
    float* sRedS = sW;          // 512 floats
    float* sRedQ = sW + 512;    // 512 floats
    if (qid == 0) {
        #pragma unroll
        for (int nt = 0; nt < 8; nt++) {
            int cc = nt * 8 + 2 * qtid;
            sRedS[warp * 64 + cc]     = sS[nt][0];
            sRedS[warp * 64 + cc + 1] = sS[nt][1];
            sRedQ[warp * 64 + cc]     = sQ[nt][0];
            sRedQ[warp * 64 + cc + 1] = sQ[nt][1];
        }
    }
    __syncthreads();
    if (tid < DD) {
        float S = 0.f, Q = 0.f;
        #pragma unroll
        for (int w = 0; w < 8; w++) {
            S += sRedS[w * 64 + tid];
            Q += sRedQ[w * 64 + tid];
        }
        atomicAdd(&g_sum[tid], S);
        atomicAdd(&g_sqs[tid], Q);
    }
}

// ---------------------------------------------------------------------------
// K4: out = h + relu( z2 * scale + shift )
// ---------------------------------------------------------------------------
__global__ void k_bn(const float4* __restrict__ h4,
                     const float* __restrict__ gamma,
                     const float* __restrict__ beta,
                     float4* __restrict__ out4) {
    __shared__ float sA[DD], sB[DD];
    if (threadIdx.x < DD) {
        const float invN = 1.0f / (float)NN;
        float m = g_sum[threadIdx.x] * invN;
        float v = g_sqs[threadIdx.x] * invN - m * m;
        float a = gamma[threadIdx.x] * rsqrtf(v + 1e-5f);
        sA[threadIdx.x] = a;
        sB[threadIdx.x] = beta[threadIdx.x] - m * a;
    }
    __syncthreads();
    int i = blockIdx.x * blockDim.x + threadIdx.x;
    if (i < NN * 16) {
        float4 z = ((const float4*)g_z2)[i];
        float4 hv = h4[i];
        int dg = (i & 15) * 4;
        float4 o;
        o.x = hv.x + fmaxf(fmaf(z.x, sA[dg + 0], sB[dg + 0]), 0.f);
        o.y = hv.y + fmaxf(fmaf(z.y, sA[dg + 1], sB[dg + 1]), 0.f);
        o.z = hv.z + fmaxf(fmaf(z.z, sA[dg + 2], sB[dg + 2]), 0.f);
        o.w = hv.w + fmaxf(fmaf(z.w, sA[dg + 3], sB[dg + 3]), 0.f);
        out4[i] = o;
    }
}

// ---------------------------------------------------------------------------
extern "C" void kernel_launch(void* const* d_in, const int* in_sizes, int n_in,
                              void* d_out, int out_size) {
    const float* h     = (const float*)d_in[0];
    const float* W1    = (const float*)d_in[1];
    const float* b1    = (const float*)d_in[2];
    const float* W2    = (const float*)d_in[3];
    const float* b2    = (const float*)d_in[4];
    const float* gamma = (const float*)d_in[5];
    const float* beta  = (const float*)d_in[6];
    const int* src     = (const int*)d_in[7];
    const int* dst     = (const int*)d_in[8];

    (void)in_sizes; (void)n_in; (void)out_size;

    k_init<<<(NN * 16 + 255) / 256, 256>>>((const float4*)h);
    k_scatter<<<(NE * 16 + 255) / 256, 256>>>((const float4*)h, src, dst);
    k_mlp<<<(NN + 127) / 128, 256>>>(W1, b1, W2, b2);
    k_bn<<<(NN * 16 + 255) / 256, 256>>>((const float4*)h, gamma, beta, (float4*)d_out);
}